// round 12
// baseline (speedup 1.0000x reference)
#include <cuda_runtime.h>
#include <math.h>

// Problem constants (fixed by the dataset)
#define NN   50000   // nodes
#define EE   800000  // edges
#define CC   5000    // clusters
#define DD   128     // in_features
#define OO   40      // out_features
#define Q10  (OO / 4)   // 10 float4 quads per row

#define FULL_MASK 0xffffffffu

typedef unsigned long long u64;

// role-split grid for kernel A
#define NB_CNT  ((EE / 4 + 255) / 256)          // 782 blocks: degree count
#define NB_GEMM ((NN + 127) / 128)              // 391 blocks: projection GEMM
#define NB_REP  ((CC + 255) / 256)              // 20 blocks: rep marking
#define NB_A    (NB_CNT + NB_GEMM + NB_REP)

// -------- scratch (__device__ globals; referenced only from device code) --
// Cleared state relies on BSS zero-init at load; k_scatter re-clears each call.
__device__ int           g_cnt[NN];
__device__ int           g_off[NN];         // bucket base (atomic-assigned)
__device__ int           g_pos[NN];         // fill cursor
__device__ int           g_total;           // bump allocator for buckets
__device__ int2          g_csc[EE];         // {src, __float_as_int(dinv[src])}
__device__ float         g_dinv[NN];
__device__ unsigned char g_is_rep[NN];
__device__ unsigned char g_needed[NN];
__device__ float4        g_z0[NN * Q10];    // projected features
__device__ float4        g_z1[NN * Q10];    // after hop 1
__device__ float4        g_lsm[CC * Q10];   // per-cluster log-softmax

// packed dual-FMA (sm_100+): d = a*b + c elementwise on 2 packed f32
__device__ __forceinline__ u64 fma2(u64 a, u64 b, u64 c) {
    u64 d;
    asm("fma.rn.f32x2 %0, %1, %2, %3;" : "=l"(d) : "l"(a), "l"(b), "l"(c));
    return d;
}
__device__ __forceinline__ float pairsum(u64 v) {
    return __uint_as_float((unsigned)(v & 0xffffffffu)) +
           __uint_as_float((unsigned)(v >> 32));
}

// ---- kernel A: three independent roles fused into one launch ------------
__global__ void kA(const int* __restrict__ dst, const int* __restrict__ rep_idx,
                   const float* __restrict__ x, const float* __restrict__ W) {
    __shared__ __align__(16) float ws[OO * 132];   // only used by GEMM role
    int blk = blockIdx.x;
    int tid = threadIdx.x;

    if (blk < NB_CNT) {                    // ---- degree count ----
        int e4 = blk * 256 + tid;
        if (e4 >= EE / 4) return;
        int4 d = reinterpret_cast<const int4*>(dst)[e4];
        atomicAdd(&g_cnt[d.x], 1);
        atomicAdd(&g_cnt[d.y], 1);
        atomicAdd(&g_cnt[d.z], 1);
        atomicAdd(&g_cnt[d.w], 1);
        return;
    }
    if (blk >= NB_CNT + NB_GEMM) {         // ---- rep marking ----
        int c = (blk - NB_CNT - NB_GEMM) * 256 + tid;
        if (c >= CC) return;
        int r = rep_idx[c];
        g_is_rep[r] = 1;
        g_needed[r] = 1;
        return;
    }

    // ---- projection GEMM: 128 nodes/block, 4 nodes x 5 outs per thread ----
    int gblk = blk - NB_CNT;
    for (int idx = tid; idx < OO * DD; idx += 256) {
        int o = idx >> 7, d = idx & 127;
        ws[o * 132 + d] = W[idx];
    }
    __syncthreads();

    int ng = tid >> 3;
    int chunk = tid & 7;
    int n0 = gblk * 128 + ng * 4;
    if (n0 >= NN) return;
    int obase = chunk * 5;

    const ulonglong2* xr[4];
    bool valid[4];
#pragma unroll
    for (int j = 0; j < 4; j++) {
        valid[j] = (n0 + j) < NN;
        int nn = valid[j] ? (n0 + j) : n0;
        xr[j] = reinterpret_cast<const ulonglong2*>(x + (size_t)nn * DD);
    }
    const ulonglong2* wsu = reinterpret_cast<const ulonglong2*>(ws);  // row stride 33

    u64 acc[4][5];
#pragma unroll
    for (int j = 0; j < 4; j++)
#pragma unroll
        for (int o = 0; o < 5; o++) acc[j][o] = 0ull;

#pragma unroll 4
    for (int d4 = 0; d4 < DD / 4; d4++) {
        ulonglong2 xp[4];
#pragma unroll
        for (int j = 0; j < 4; j++) xp[j] = xr[j][d4];
#pragma unroll
        for (int o = 0; o < 5; o++) {
            ulonglong2 wp = wsu[(obase + o) * 33 + d4];
#pragma unroll
            for (int j = 0; j < 4; j++) {
                acc[j][o] = fma2(xp[j].x, wp.x, acc[j][o]);
                acc[j][o] = fma2(xp[j].y, wp.y, acc[j][o]);
            }
        }
    }

    float* z0 = reinterpret_cast<float*>(g_z0);
#pragma unroll
    for (int j = 0; j < 4; j++) {
        if (!valid[j]) continue;
        float* row = z0 + (size_t)(n0 + j) * OO + obase;
#pragma unroll
        for (int o = 0; o < 5; o++) row[o] = pairsum(acc[j][o]);
    }
}

// prep: block-local exclusive scan + ONE bump atomic per block (was 50k
// atomics to one address -> ~43k serialized LTS cycles). Emits bucket base,
// fill cursor, dinv.
__global__ void k_prep(void) {
    __shared__ int sh[256];
    __shared__ int base;
    int tid = threadIdx.x;
    int i = blockIdx.x * 256 + tid;
    int c = (i < NN) ? g_cnt[i] : 0;
    sh[tid] = c;
    __syncthreads();
#pragma unroll
    for (int off = 1; off < 256; off <<= 1) {
        int t = (tid >= off) ? sh[tid - off] : 0;
        __syncthreads();
        sh[tid] += t;
        __syncthreads();
    }
    if (tid == 255) base = atomicAdd(&g_total, sh[255]);
    __syncthreads();
    if (i < NN) {
        int o = base + sh[tid] - c;     // block-exclusive + block base
        g_off[i] = o;
        g_pos[i] = o;
        g_dinv[i] = rsqrtf((float)(c + 1));
    }
}

// fill CSC buckets; pack dinv[src]; mark hop-1 needed set (srcs feeding reps)
__global__ void k_fill(const int* __restrict__ src, const int* __restrict__ dst) {
    int e4 = blockIdx.x * blockDim.x + threadIdx.x;
    if (e4 >= EE / 4) return;
    int4 s = reinterpret_cast<const int4*>(src)[e4];
    int4 d = reinterpret_cast<const int4*>(dst)[e4];
    int p;
    p = atomicAdd(&g_pos[d.x], 1); g_csc[p] = make_int2(s.x, __float_as_int(g_dinv[s.x]));
    p = atomicAdd(&g_pos[d.y], 1); g_csc[p] = make_int2(s.y, __float_as_int(g_dinv[s.y]));
    p = atomicAdd(&g_pos[d.z], 1); g_csc[p] = make_int2(s.z, __float_as_int(g_dinv[s.z]));
    p = atomicAdd(&g_pos[d.w], 1); g_csc[p] = make_int2(s.w, __float_as_int(g_dinv[s.w]));
    if (g_is_rep[d.x]) g_needed[s.x] = 1;
    if (g_is_rep[d.y]) g_needed[s.y] = 1;
    if (g_is_rep[d.z]) g_needed[s.z] = 1;
    if (g_is_rep[d.w]) g_needed[s.w] = 1;
}

// hop 1 gather (needed nodes only): thread per (node, float4 quad).
// 4-edge unroll -> 8 independent loads in flight per iteration.
__global__ void k_gather1(void) {
    int idx = blockIdx.x * blockDim.x + threadIdx.x;
    if (idx >= NN * Q10) return;
    int n = idx / Q10;
    int q = idx - n * Q10;
    if (!g_needed[n]) return;
    float dn = g_dinv[n];
    float w = dn * dn;
    float4 a = g_z0[(size_t)n * Q10 + q];
    float4 acc = make_float4(w * a.x, w * a.y, w * a.z, w * a.w);
    int beg = g_off[n], end = beg + g_cnt[n];
    int i = beg;
    for (; i + 3 < end; i += 4) {
        int2 e0 = g_csc[i],     e1 = g_csc[i + 1];
        int2 e2 = g_csc[i + 2], e3 = g_csc[i + 3];
        float4 v0 = g_z0[(size_t)e0.x * Q10 + q];
        float4 v1 = g_z0[(size_t)e1.x * Q10 + q];
        float4 v2 = g_z0[(size_t)e2.x * Q10 + q];
        float4 v3 = g_z0[(size_t)e3.x * Q10 + q];
        float c0 = __int_as_float(e0.y) * dn;
        float c1 = __int_as_float(e1.y) * dn;
        float c2 = __int_as_float(e2.y) * dn;
        float c3 = __int_as_float(e3.y) * dn;
        acc.x += c0 * v0.x + c1 * v1.x + c2 * v2.x + c3 * v3.x;
        acc.y += c0 * v0.y + c1 * v1.y + c2 * v2.y + c3 * v3.y;
        acc.z += c0 * v0.z + c1 * v1.z + c2 * v2.z + c3 * v3.z;
        acc.w += c0 * v0.w + c1 * v1.w + c2 * v2.w + c3 * v3.w;
    }
#pragma unroll 1
    for (; i < end; i++) {
        int2 e0 = g_csc[i];
        float4 v0 = g_z0[(size_t)e0.x * Q10 + q];
        float c0 = __int_as_float(e0.y) * dn;
        acc.x += c0 * v0.x; acc.y += c0 * v0.y;
        acc.z += c0 * v0.z; acc.w += c0 * v0.w;
    }
    g_z1[(size_t)n * Q10 + q] = acc;
}

// hop 2 + bias + log_softmax fused: warp per cluster, 4-edge unroll
__global__ void k_gather2_lsm(const int* __restrict__ rep_idx, const float* __restrict__ b) {
    int c = (blockIdx.x * blockDim.x + threadIdx.x) >> 5;
    if (c >= CC) return;
    int lane = threadIdx.x & 31;
    int n = rep_idx[c];
    float dn = g_dinv[n];
    const float* z1 = reinterpret_cast<const float*>(g_z1);
    const float* z1n = z1 + (size_t)n * OO;
    float acc1 = dn * dn * z1n[lane];
    float acc2 = (lane < OO - 32) ? dn * dn * z1n[32 + lane] : 0.f;
    int beg = g_off[n], end = beg + g_cnt[n];
    int i = beg;
    for (; i + 3 < end; i += 4) {
        int2 e0 = g_csc[i],     e1 = g_csc[i + 1];
        int2 e2 = g_csc[i + 2], e3 = g_csc[i + 3];
        float f0 = __int_as_float(e0.y) * dn;
        float f1 = __int_as_float(e1.y) * dn;
        float f2 = __int_as_float(e2.y) * dn;
        float f3 = __int_as_float(e3.y) * dn;
        const float* p0 = z1 + (size_t)e0.x * OO;
        const float* p1 = z1 + (size_t)e1.x * OO;
        const float* p2 = z1 + (size_t)e2.x * OO;
        const float* p3 = z1 + (size_t)e3.x * OO;
        acc1 += f0 * p0[lane] + f1 * p1[lane] + f2 * p2[lane] + f3 * p3[lane];
        if (lane < OO - 32)
            acc2 += f0 * p0[32 + lane] + f1 * p1[32 + lane]
                  + f2 * p2[32 + lane] + f3 * p3[32 + lane];
    }
#pragma unroll 1
    for (; i < end; i++) {
        int2 e = g_csc[i];
        float cf = __int_as_float(e.y) * dn;
        const float* zs = z1 + (size_t)e.x * OO;
        acc1 += cf * zs[lane];
        if (lane < OO - 32) acc2 += cf * zs[32 + lane];
    }
    float v1 = acc1 + b[lane];
    float v2 = (lane < OO - 32) ? (acc2 + b[32 + lane]) : -INFINITY;
    float m = fmaxf(v1, v2);
#pragma unroll
    for (int off = 16; off > 0; off >>= 1)
        m = fmaxf(m, __shfl_xor_sync(FULL_MASK, m, off));
    float s = expf(v1 - m) + ((lane < OO - 32) ? expf(v2 - m) : 0.f);
#pragma unroll
    for (int off = 16; off > 0; off >>= 1)
        s += __shfl_xor_sync(FULL_MASK, s, off);
    float ls = m + logf(s);
    float* lc = reinterpret_cast<float*>(g_lsm) + (size_t)c * OO;
    lc[lane] = v1 - ls;
    if (lane < OO - 32) lc[32 + lane] = v2 - ls;
}

// out[n] = lsm[cluster[n]] (float4); also reset all scratch for next call
__global__ void k_scatter(const int* __restrict__ cluster_index, float4* __restrict__ out) {
    int idx = blockIdx.x * blockDim.x + threadIdx.x;
    if (idx >= NN * Q10) return;
    int n = idx / Q10;
    int q = idx - n * Q10;
    if (q == 0) {                 // one thread per node clears scratch
        g_cnt[n] = 0;
        g_needed[n] = 0;
        g_is_rep[n] = 0;
        if (n == 0) g_total = 0;
    }
    out[idx] = g_lsm[(size_t)cluster_index[n] * Q10 + q];
}

// -------- launch ---------------------------------------------------------
extern "C" void kernel_launch(void* const* d_in, const int* in_sizes, int n_in,
                              void* d_out, int out_size) {
    const float* x       = (const float*)d_in[0];            // [N,128]
    const int*   eidx    = (const int*)d_in[1];              // [2,E] row-major
    const int*   cluster = (const int*)d_in[2];              // [N]
    const int*   rep_idx = (const int*)d_in[3];              // [C]
    const float* W       = (const float*)d_in[4];            // [40,128]
    const float* b       = (const float*)d_in[5];            // [40]
    float4*      out     = (float4*)d_out;                   // [N,40]

    const int* src = eidx;        // edge_index[0]
    const int* dst = eidx + EE;   // edge_index[1]

    const int T = 256;
    dim3 bE4((EE / 4 + T - 1) / T);
    dim3 bN((NN + T - 1) / T);
    dim3 bNQ((NN * Q10 + T - 1) / T);
    dim3 bClWarp((CC * 32 + T - 1) / T);

    kA<<<NB_A, T>>>(dst, rep_idx, x, W);
    k_prep<<<bN, T>>>();
    k_fill<<<bE4, T>>>(src, dst);
    k_gather1<<<bNQ, T>>>();
    k_gather2_lsm<<<bClWarp, T>>>(rep_idx, b);
    k_scatter<<<bNQ, T>>>(cluster, out);
}

// round 14
// speedup vs baseline: 1.3552x; 1.3552x over previous
#include <cuda_runtime.h>
#include <math.h>

// Problem constants (fixed by the dataset)
#define NN   50000   // nodes
#define EE   800000  // edges
#define CC   5000    // clusters
#define DD   128     // in_features
#define OO   40      // out_features
#define Q10  (OO / 4)   // 10 float4 quads per row

#define FULL_MASK 0xffffffffu

typedef unsigned long long u64;

// role-split grid for kernel A
#define NB_CNT  ((EE / 4 + 255) / 256)          // 782 blocks: degree count
#define NB_GEMM ((NN + 127) / 128)              // 391 blocks: projection GEMM
#define NB_REP  ((CC + 255) / 256)              // 20 blocks: rep marking
#define NB_A    (NB_CNT + NB_GEMM + NB_REP)

// -------- scratch (__device__ globals; referenced only from device code) --
// Cleared state relies on BSS zero-init at load; k_scatter re-clears each call.
__device__ int           g_cnt[NN];
__device__ int           g_off[NN];         // bucket base (block-scan assigned)
__device__ int           g_pos[NN];         // fill cursor
__device__ int           g_total;           // bump allocator (one atomic per block)
__device__ int2          g_csc[EE];         // {src, __float_as_int(dinv[src])}
__device__ float         g_dinv[NN];
__device__ unsigned char g_is_rep[NN];
__device__ unsigned char g_needed[NN];
__device__ float4        g_z0[NN * Q10];    // projected features
__device__ float4        g_z1[NN * Q10];    // after hop 1
__device__ float4        g_lsm[CC * Q10];   // per-cluster log-softmax

// packed dual-FMA (sm_100+): d = a*b + c elementwise on 2 packed f32
__device__ __forceinline__ u64 fma2(u64 a, u64 b, u64 c) {
    u64 d;
    asm("fma.rn.f32x2 %0, %1, %2, %3;" : "=l"(d) : "l"(a), "l"(b), "l"(c));
    return d;
}
__device__ __forceinline__ float pairsum(u64 v) {
    return __uint_as_float((unsigned)(v & 0xffffffffu)) +
           __uint_as_float((unsigned)(v >> 32));
}

// ---- kernel A: three independent roles fused into one launch ------------
__global__ void kA(const int* __restrict__ dst, const int* __restrict__ rep_idx,
                   const float* __restrict__ x, const float* __restrict__ W) {
    __shared__ __align__(16) float ws[OO * 132];   // only used by GEMM role
    int blk = blockIdx.x;
    int tid = threadIdx.x;

    if (blk < NB_CNT) {                    // ---- degree count ----
        int e4 = blk * 256 + tid;
        if (e4 >= EE / 4) return;
        int4 d = reinterpret_cast<const int4*>(dst)[e4];
        atomicAdd(&g_cnt[d.x], 1);
        atomicAdd(&g_cnt[d.y], 1);
        atomicAdd(&g_cnt[d.z], 1);
        atomicAdd(&g_cnt[d.w], 1);
        return;
    }
    if (blk >= NB_CNT + NB_GEMM) {         // ---- rep marking ----
        int c = (blk - NB_CNT - NB_GEMM) * 256 + tid;
        if (c >= CC) return;
        int r = rep_idx[c];
        g_is_rep[r] = 1;
        g_needed[r] = 1;
        return;
    }

    // ---- projection GEMM: 128 nodes/block, 4 nodes x 5 outs per thread ----
    int gblk = blk - NB_CNT;
    for (int idx = tid; idx < OO * DD; idx += 256) {
        int o = idx >> 7, d = idx & 127;
        ws[o * 132 + d] = W[idx];
    }
    __syncthreads();

    int ng = tid >> 3;
    int chunk = tid & 7;
    int n0 = gblk * 128 + ng * 4;
    if (n0 >= NN) return;
    int obase = chunk * 5;

    const ulonglong2* xr[4];
    bool valid[4];
#pragma unroll
    for (int j = 0; j < 4; j++) {
        valid[j] = (n0 + j) < NN;
        int nn = valid[j] ? (n0 + j) : n0;
        xr[j] = reinterpret_cast<const ulonglong2*>(x + (size_t)nn * DD);
    }
    const ulonglong2* wsu = reinterpret_cast<const ulonglong2*>(ws);  // row stride 33

    u64 acc[4][5];
#pragma unroll
    for (int j = 0; j < 4; j++)
#pragma unroll
        for (int o = 0; o < 5; o++) acc[j][o] = 0ull;

#pragma unroll 4
    for (int d4 = 0; d4 < DD / 4; d4++) {
        ulonglong2 xp[4];
#pragma unroll
        for (int j = 0; j < 4; j++) xp[j] = xr[j][d4];
#pragma unroll
        for (int o = 0; o < 5; o++) {
            ulonglong2 wp = wsu[(obase + o) * 33 + d4];
#pragma unroll
            for (int j = 0; j < 4; j++) {
                acc[j][o] = fma2(xp[j].x, wp.x, acc[j][o]);
                acc[j][o] = fma2(xp[j].y, wp.y, acc[j][o]);
            }
        }
    }

    float* z0 = reinterpret_cast<float*>(g_z0);
#pragma unroll
    for (int j = 0; j < 4; j++) {
        if (!valid[j]) continue;
        float* row = z0 + (size_t)(n0 + j) * OO + obase;
#pragma unroll
        for (int o = 0; o < 5; o++) row[o] = pairsum(acc[j][o]);
    }
}

// prep: block-local exclusive scan + ONE bump atomic per block.
// (R10's 50k atomicAdds to one address serialize at ~0.854 cyc each on one
//  LTS atomic ALU -> ~24 us; this is 196 atomics instead.)
__global__ void k_prep(void) {
    __shared__ int sh[256];
    __shared__ int base;
    int tid = threadIdx.x;
    int i = blockIdx.x * 256 + tid;
    int c = (i < NN) ? g_cnt[i] : 0;
    sh[tid] = c;
    __syncthreads();
#pragma unroll
    for (int off = 1; off < 256; off <<= 1) {
        int t = (tid >= off) ? sh[tid - off] : 0;
        __syncthreads();
        sh[tid] += t;
        __syncthreads();
    }
    if (tid == 255) base = atomicAdd(&g_total, sh[255]);
    __syncthreads();
    if (i < NN) {
        int o = base + sh[tid] - c;     // block-exclusive + block base
        g_off[i] = o;
        g_pos[i] = o;
        g_dinv[i] = rsqrtf((float)(c + 1));
    }
}

// fill CSC buckets; pack dinv[src]; mark hop-1 needed set (srcs feeding reps)
__global__ void k_fill(const int* __restrict__ src, const int* __restrict__ dst) {
    int e4 = blockIdx.x * blockDim.x + threadIdx.x;
    if (e4 >= EE / 4) return;
    int4 s = reinterpret_cast<const int4*>(src)[e4];
    int4 d = reinterpret_cast<const int4*>(dst)[e4];
    int p;
    p = atomicAdd(&g_pos[d.x], 1); g_csc[p] = make_int2(s.x, __float_as_int(g_dinv[s.x]));
    p = atomicAdd(&g_pos[d.y], 1); g_csc[p] = make_int2(s.y, __float_as_int(g_dinv[s.y]));
    p = atomicAdd(&g_pos[d.z], 1); g_csc[p] = make_int2(s.z, __float_as_int(g_dinv[s.z]));
    p = atomicAdd(&g_pos[d.w], 1); g_csc[p] = make_int2(s.w, __float_as_int(g_dinv[s.w]));
    if (g_is_rep[d.x]) g_needed[s.x] = 1;
    if (g_is_rep[d.y]) g_needed[s.y] = 1;
    if (g_is_rep[d.z]) g_needed[s.z] = 1;
    if (g_is_rep[d.w]) g_needed[s.w] = 1;
}

// hop 1 gather (needed nodes only): thread per (node, float4 quad).
// 2-edge unroll (proven best in R10; deeper unroll regresses via L1tex-queue
// contention on this chip).
__global__ void k_gather1(void) {
    int idx = blockIdx.x * blockDim.x + threadIdx.x;
    if (idx >= NN * Q10) return;
    int n = idx / Q10;
    int q = idx - n * Q10;
    if (!g_needed[n]) return;
    float dn = g_dinv[n];
    float w = dn * dn;
    float4 a = g_z0[(size_t)n * Q10 + q];
    float4 acc = make_float4(w * a.x, w * a.y, w * a.z, w * a.w);
    int beg = g_off[n], end = beg + g_cnt[n];
    int i = beg;
    for (; i + 1 < end; i += 2) {
        int2 e0 = g_csc[i], e1 = g_csc[i + 1];
        float4 v0 = g_z0[(size_t)e0.x * Q10 + q];
        float4 v1 = g_z0[(size_t)e1.x * Q10 + q];
        float c0 = __int_as_float(e0.y) * dn;
        float c1 = __int_as_float(e1.y) * dn;
        acc.x += c0 * v0.x + c1 * v1.x;
        acc.y += c0 * v0.y + c1 * v1.y;
        acc.z += c0 * v0.z + c1 * v1.z;
        acc.w += c0 * v0.w + c1 * v1.w;
    }
    if (i < end) {
        int2 e0 = g_csc[i];
        float4 v0 = g_z0[(size_t)e0.x * Q10 + q];
        float c0 = __int_as_float(e0.y) * dn;
        acc.x += c0 * v0.x; acc.y += c0 * v0.y;
        acc.z += c0 * v0.z; acc.w += c0 * v0.w;
    }
    g_z1[(size_t)n * Q10 + q] = acc;
}

// hop 2 + bias + log_softmax fused: warp per cluster (simple loop, R10 form)
__global__ void k_gather2_lsm(const int* __restrict__ rep_idx, const float* __restrict__ b) {
    int c = (blockIdx.x * blockDim.x + threadIdx.x) >> 5;
    if (c >= CC) return;
    int lane = threadIdx.x & 31;
    int n = rep_idx[c];
    float dn = g_dinv[n];
    const float* z1 = reinterpret_cast<const float*>(g_z1);
    const float* z1n = z1 + (size_t)n * OO;
    float acc1 = dn * dn * z1n[lane];
    float acc2 = (lane < OO - 32) ? dn * dn * z1n[32 + lane] : 0.f;
    int beg = g_off[n], end = beg + g_cnt[n];
    for (int i = beg; i < end; i++) {
        int2 e = g_csc[i];
        float cf = __int_as_float(e.y) * dn;
        const float* zs = z1 + (size_t)e.x * OO;
        acc1 += cf * zs[lane];
        if (lane < OO - 32) acc2 += cf * zs[32 + lane];
    }
    float v1 = acc1 + b[lane];
    float v2 = (lane < OO - 32) ? (acc2 + b[32 + lane]) : -INFINITY;
    float m = fmaxf(v1, v2);
#pragma unroll
    for (int off = 16; off > 0; off >>= 1)
        m = fmaxf(m, __shfl_xor_sync(FULL_MASK, m, off));
    float s = expf(v1 - m) + ((lane < OO - 32) ? expf(v2 - m) : 0.f);
#pragma unroll
    for (int off = 16; off > 0; off >>= 1)
        s += __shfl_xor_sync(FULL_MASK, s, off);
    float ls = m + logf(s);
    float* lc = reinterpret_cast<float*>(g_lsm) + (size_t)c * OO;
    lc[lane] = v1 - ls;
    if (lane < OO - 32) lc[32 + lane] = v2 - ls;
}

// out[n] = lsm[cluster[n]] (float4); also reset all scratch for next call
__global__ void k_scatter(const int* __restrict__ cluster_index, float4* __restrict__ out) {
    int idx = blockIdx.x * blockDim.x + threadIdx.x;
    if (idx >= NN * Q10) return;
    int n = idx / Q10;
    int q = idx - n * Q10;
    if (q == 0) {                 // one thread per node clears scratch
        g_cnt[n] = 0;
        g_needed[n] = 0;
        g_is_rep[n] = 0;
        if (n == 0) g_total = 0;
    }
    out[idx] = g_lsm[(size_t)cluster_index[n] * Q10 + q];
}

// -------- launch ---------------------------------------------------------
extern "C" void kernel_launch(void* const* d_in, const int* in_sizes, int n_in,
                              void* d_out, int out_size) {
    const float* x       = (const float*)d_in[0];            // [N,128]
    const int*   eidx    = (const int*)d_in[1];              // [2,E] row-major
    const int*   cluster = (const int*)d_in[2];              // [N]
    const int*   rep_idx = (const int*)d_in[3];              // [C]
    const float* W       = (const float*)d_in[4];            // [40,128]
    const float* b       = (const float*)d_in[5];            // [40]
    float4*      out     = (float4*)d_out;                   // [N,40]

    const int* src = eidx;        // edge_index[0]
    const int* dst = eidx + EE;   // edge_index[1]

    const int T = 256;
    dim3 bE4((EE / 4 + T - 1) / T);
    dim3 bN((NN + T - 1) / T);
    dim3 bNQ((NN * Q10 + T - 1) / T);
    dim3 bClWarp((CC * 32 + T - 1) / T);

    kA<<<NB_A, T>>>(dst, rep_idx, x, W);
    k_prep<<<bN, T>>>();
    k_fill<<<bE4, T>>>(src, dst);
    k_gather1<<<bNQ, T>>>();
    k_gather2_lsm<<<bClWarp, T>>>(rep_idx, b);
    k_scatter<<<bNQ, T>>>(cluster, out);
}

// round 16
// speedup vs baseline: 1.4270x; 1.0530x over previous
#include <cuda_runtime.h>
#include <math.h>

// Problem constants (fixed by the dataset)
#define NN   50000   // nodes
#define EE   800000  // edges
#define CC   5000    // clusters
#define DD   128     // in_features
#define OO   40      // out_features
#define Q10  (OO / 4)   // 10 float4 quads per row

#define FULL_MASK 0xffffffffu

typedef unsigned long long u64;

// role-split grid for kernel A
#define NB_CNT  ((EE / 4 + 255) / 256)          // 782 blocks: degree count
#define NB_GEMM ((NN + 127) / 128)              // 391 blocks: projection GEMM
#define NB_REP  ((CC + 255) / 256)              // 20 blocks: rep marking
#define NB_A    (NB_CNT + NB_GEMM + NB_REP)

// -------- scratch (__device__ globals; referenced only from device code) --
// Cleared state relies on BSS zero-init at load; k_scatter re-clears each call.
__device__ int           g_cnt[NN];
__device__ int           g_off[NN];         // bucket base (block-scan assigned)
__device__ int           g_pos[NN];         // fill cursor
__device__ int           g_total;           // bump allocator (one atomic per block)
__device__ int2          g_csc[EE];         // {src, __float_as_int(dinv[src])}
__device__ float         g_dinv[NN];
__device__ unsigned char g_is_rep[NN];
__device__ unsigned char g_needed[NN];
__device__ float4        g_z0[NN * Q10];    // projected features
__device__ float4        g_z1[NN * Q10];    // after hop 1
__device__ float4        g_lsm[CC * Q10];   // per-cluster log-softmax

// packed dual-FMA (sm_100+): d = a*b + c elementwise on 2 packed f32
__device__ __forceinline__ u64 fma2(u64 a, u64 b, u64 c) {
    u64 d;
    asm("fma.rn.f32x2 %0, %1, %2, %3;" : "=l"(d) : "l"(a), "l"(b), "l"(c));
    return d;
}
__device__ __forceinline__ float pairsum(u64 v) {
    return __uint_as_float((unsigned)(v & 0xffffffffu)) +
           __uint_as_float((unsigned)(v >> 32));
}

// ---- kernel A: three independent roles fused into one launch ------------
__global__ void kA(const int* __restrict__ dst, const int* __restrict__ rep_idx,
                   const float* __restrict__ x, const float* __restrict__ W) {
    __shared__ __align__(16) float ws[OO * 132];   // only used by GEMM role
    int blk = blockIdx.x;
    int tid = threadIdx.x;

    if (blk < NB_CNT) {                    // ---- degree count ----
        int e4 = blk * 256 + tid;
        if (e4 >= EE / 4) return;
        int4 d = reinterpret_cast<const int4*>(dst)[e4];
        atomicAdd(&g_cnt[d.x], 1);
        atomicAdd(&g_cnt[d.y], 1);
        atomicAdd(&g_cnt[d.z], 1);
        atomicAdd(&g_cnt[d.w], 1);
        return;
    }
    if (blk >= NB_CNT + NB_GEMM) {         // ---- rep marking ----
        int c = (blk - NB_CNT - NB_GEMM) * 256 + tid;
        if (c >= CC) return;
        int r = rep_idx[c];
        g_is_rep[r] = 1;
        g_needed[r] = 1;
        return;
    }

    // ---- projection GEMM: 128 nodes/block, 4 nodes x 5 outs per thread ----
    int gblk = blk - NB_CNT;
    for (int idx = tid; idx < OO * DD; idx += 256) {
        int o = idx >> 7, d = idx & 127;
        ws[o * 132 + d] = W[idx];
    }
    __syncthreads();

    int ng = tid >> 3;
    int chunk = tid & 7;
    int n0 = gblk * 128 + ng * 4;
    if (n0 >= NN) return;
    int obase = chunk * 5;

    const ulonglong2* xr[4];
    bool valid[4];
#pragma unroll
    for (int j = 0; j < 4; j++) {
        valid[j] = (n0 + j) < NN;
        int nn = valid[j] ? (n0 + j) : n0;
        xr[j] = reinterpret_cast<const ulonglong2*>(x + (size_t)nn * DD);
    }
    const ulonglong2* wsu = reinterpret_cast<const ulonglong2*>(ws);  // row stride 33

    u64 acc[4][5];
#pragma unroll
    for (int j = 0; j < 4; j++)
#pragma unroll
        for (int o = 0; o < 5; o++) acc[j][o] = 0ull;

#pragma unroll 4
    for (int d4 = 0; d4 < DD / 4; d4++) {
        ulonglong2 xp[4];
#pragma unroll
        for (int j = 0; j < 4; j++) xp[j] = xr[j][d4];
#pragma unroll
        for (int o = 0; o < 5; o++) {
            ulonglong2 wp = wsu[(obase + o) * 33 + d4];
#pragma unroll
            for (int j = 0; j < 4; j++) {
                acc[j][o] = fma2(xp[j].x, wp.x, acc[j][o]);
                acc[j][o] = fma2(xp[j].y, wp.y, acc[j][o]);
            }
        }
    }

    float* z0 = reinterpret_cast<float*>(g_z0);
#pragma unroll
    for (int j = 0; j < 4; j++) {
        if (!valid[j]) continue;
        float* row = z0 + (size_t)(n0 + j) * OO + obase;
#pragma unroll
        for (int o = 0; o < 5; o++) row[o] = pairsum(acc[j][o]);
    }
}

// prep: block-local exclusive scan + ONE bump atomic per block
__global__ void k_prep(void) {
    __shared__ int sh[256];
    __shared__ int base;
    int tid = threadIdx.x;
    int i = blockIdx.x * 256 + tid;
    int c = (i < NN) ? g_cnt[i] : 0;
    sh[tid] = c;
    __syncthreads();
#pragma unroll
    for (int off = 1; off < 256; off <<= 1) {
        int t = (tid >= off) ? sh[tid - off] : 0;
        __syncthreads();
        sh[tid] += t;
        __syncthreads();
    }
    if (tid == 255) base = atomicAdd(&g_total, sh[255]);
    __syncthreads();
    if (i < NN) {
        int o = base + sh[tid] - c;     // block-exclusive + block base
        g_off[i] = o;
        g_pos[i] = o;
        g_dinv[i] = rsqrtf((float)(c + 1));
    }
}

// fill CSC buckets; pack dinv[src]; mark hop-1 needed set (srcs feeding reps)
__global__ void __launch_bounds__(256, 8)
k_fill(const int* __restrict__ src, const int* __restrict__ dst) {
    int e4 = blockIdx.x * blockDim.x + threadIdx.x;
    if (e4 >= EE / 4) return;
    int4 s = reinterpret_cast<const int4*>(src)[e4];
    int4 d = reinterpret_cast<const int4*>(dst)[e4];
    int p;
    p = atomicAdd(&g_pos[d.x], 1); g_csc[p] = make_int2(s.x, __float_as_int(g_dinv[s.x]));
    p = atomicAdd(&g_pos[d.y], 1); g_csc[p] = make_int2(s.y, __float_as_int(g_dinv[s.y]));
    p = atomicAdd(&g_pos[d.z], 1); g_csc[p] = make_int2(s.z, __float_as_int(g_dinv[s.z]));
    p = atomicAdd(&g_pos[d.w], 1); g_csc[p] = make_int2(s.w, __float_as_int(g_dinv[s.w]));
    if (g_is_rep[d.x]) g_needed[s.x] = 1;
    if (g_is_rep[d.y]) g_needed[s.y] = 1;
    if (g_is_rep[d.z]) g_needed[s.z] = 1;
    if (g_is_rep[d.w]) g_needed[s.w] = 1;
}

// hop 1 gather (needed nodes only): thread per (node, float4 quad).
// 2-edge unroll (deeper regresses: L1tex-queue contention, R11).
// launch_bounds(256,8): cap regs at 32 -> 100% occupancy (was 38 regs / 57%).
__global__ void __launch_bounds__(256, 8)
k_gather1(void) {
    int idx = blockIdx.x * blockDim.x + threadIdx.x;
    if (idx >= NN * Q10) return;
    int n = idx / Q10;
    int q = idx - n * Q10;
    if (!g_needed[n]) return;
    float dn = g_dinv[n];
    float w = dn * dn;
    float4 a = g_z0[(size_t)n * Q10 + q];
    float4 acc = make_float4(w * a.x, w * a.y, w * a.z, w * a.w);
    int beg = g_off[n], end = beg + g_cnt[n];
    int i = beg;
    for (; i + 1 < end; i += 2) {
        int2 e0 = g_csc[i], e1 = g_csc[i + 1];
        float4 v0 = g_z0[(size_t)e0.x * Q10 + q];
        float4 v1 = g_z0[(size_t)e1.x * Q10 + q];
        float c0 = __int_as_float(e0.y) * dn;
        float c1 = __int_as_float(e1.y) * dn;
        acc.x += c0 * v0.x + c1 * v1.x;
        acc.y += c0 * v0.y + c1 * v1.y;
        acc.z += c0 * v0.z + c1 * v1.z;
        acc.w += c0 * v0.w + c1 * v1.w;
    }
    if (i < end) {
        int2 e0 = g_csc[i];
        float4 v0 = g_z0[(size_t)e0.x * Q10 + q];
        float c0 = __int_as_float(e0.y) * dn;
        acc.x += c0 * v0.x; acc.y += c0 * v0.y;
        acc.z += c0 * v0.z; acc.w += c0 * v0.w;
    }
    g_z1[(size_t)n * Q10 + q] = acc;
}

// hop 2 + bias + log_softmax fused: warp per cluster
__global__ void __launch_bounds__(256, 8)
k_gather2_lsm(const int* __restrict__ rep_idx, const float* __restrict__ b) {
    int c = (blockIdx.x * blockDim.x + threadIdx.x) >> 5;
    if (c >= CC) return;
    int lane = threadIdx.x & 31;
    int n = rep_idx[c];
    float dn = g_dinv[n];
    const float* z1 = reinterpret_cast<const float*>(g_z1);
    const float* z1n = z1 + (size_t)n * OO;
    float acc1 = dn * dn * z1n[lane];
    float acc2 = (lane < OO - 32) ? dn * dn * z1n[32 + lane] : 0.f;
    int beg = g_off[n], end = beg + g_cnt[n];
    for (int i = beg; i < end; i++) {
        int2 e = g_csc[i];
        float cf = __int_as_float(e.y) * dn;
        const float* zs = z1 + (size_t)e.x * OO;
        acc1 += cf * zs[lane];
        if (lane < OO - 32) acc2 += cf * zs[32 + lane];
    }
    float v1 = acc1 + b[lane];
    float v2 = (lane < OO - 32) ? (acc2 + b[32 + lane]) : -INFINITY;
    float m = fmaxf(v1, v2);
#pragma unroll
    for (int off = 16; off > 0; off >>= 1)
        m = fmaxf(m, __shfl_xor_sync(FULL_MASK, m, off));
    float s = expf(v1 - m) + ((lane < OO - 32) ? expf(v2 - m) : 0.f);
#pragma unroll
    for (int off = 16; off > 0; off >>= 1)
        s += __shfl_xor_sync(FULL_MASK, s, off);
    float ls = m + logf(s);
    float* lc = reinterpret_cast<float*>(g_lsm) + (size_t)c * OO;
    lc[lane] = v1 - ls;
    if (lane < OO - 32) lc[32 + lane] = v2 - ls;
}

// out[n] = lsm[cluster[n]] (float4); also reset all scratch for next call
__global__ void __launch_bounds__(256, 8)
k_scatter(const int* __restrict__ cluster_index, float4* __restrict__ out) {
    int idx = blockIdx.x * blockDim.x + threadIdx.x;
    if (idx >= NN * Q10) return;
    int n = idx / Q10;
    int q = idx - n * Q10;
    if (q == 0) {                 // one thread per node clears scratch
        g_cnt[n] = 0;
        g_needed[n] = 0;
        g_is_rep[n] = 0;
        if (n == 0) g_total = 0;
    }
    out[idx] = g_lsm[(size_t)cluster_index[n] * Q10 + q];
}

// -------- launch ---------------------------------------------------------
extern "C" void kernel_launch(void* const* d_in, const int* in_sizes, int n_in,
                              void* d_out, int out_size) {
    const float* x       = (const float*)d_in[0];            // [N,128]
    const int*   eidx    = (const int*)d_in[1];              // [2,E] row-major
    const int*   cluster = (const int*)d_in[2];              // [N]
    const int*   rep_idx = (const int*)d_in[3];              // [C]
    const float* W       = (const float*)d_in[4];            // [40,128]
    const float* b       = (const float*)d_in[5];            // [40]
    float4*      out     = (float4*)d_out;                   // [N,40]

    const int* src = eidx;        // edge_index[0]
    const int* dst = eidx + EE;   // edge_index[1]

    const int T = 256;
    dim3 bE4((EE / 4 + T - 1) / T);
    dim3 bN((NN + T - 1) / T);
    dim3 bNQ((NN * Q10 + T - 1) / T);
    dim3 bClWarp((CC * 32 + T - 1) / T);

    kA<<<NB_A, T>>>(dst, rep_idx, x, W);
    k_prep<<<bN, T>>>();
    k_fill<<<bE4, T>>>(src, dst);
    k_gather1<<<bNQ, T>>>();
    k_gather2_lsm<<<bClWarp, T>>>(rep_idx, b);
    k_scatter<<<bNQ, T>>>(cluster, out);
}